// round 6
// baseline (speedup 1.0000x reference)
#include <cuda_runtime.h>

#define NN 50000
#define NE 800000
#define EMB 64
#define NL 4
#define BN_EPS 1e-5f

typedef unsigned long long ull;

__device__ float  g_h [NN*EMB];
__device__ float  g_u [NN*EMB];
__device__ float  g_t1[NN*EMB];
__device__ float  g_t2[NN*EMB];
__device__ int    g_deg[NN];
__device__ int    g_off[NN+1];
__device__ int    g_cur[NN];
__device__ float2 g_csr[NE];
__device__ float  g_stats[NL][2][2*EMB];   // [layer][stage][sum|ss]

__device__ __forceinline__ ull pack2(float a, float b){
    ull r; asm("mov.b64 %0, {%1, %2};" : "=l"(r) : "f"(a), "f"(b)); return r;
}
__device__ __forceinline__ float2 unpack2(ull v){
    float2 r; asm("mov.b64 {%0, %1}, %2;" : "=f"(r.x), "=f"(r.y) : "l"(v)); return r;
}
__device__ __forceinline__ void ffma2(ull &d, ull a, ull b){
    asm("fma.rn.f32x2 %0, %1, %2, %0;" : "+l"(d) : "l"(a), "l"(b));
}

__global__ void k_init(){
    int i = blockIdx.x*blockDim.x + threadIdx.x;
    if (i < NN) g_deg[i] = 0;
    if (i < NL*2*2*EMB) ((float*)g_stats)[i] = 0.f;
}

__global__ void k_hist(const int* __restrict__ ei){
    int e = blockIdx.x*blockDim.x + threadIdx.x;
    if (e < NE) atomicAdd(&g_deg[ei[NE + e]], 1);
}

// coalesced block-strided scan (R2 version — proven)
__global__ void k_scan(){
    __shared__ int wsum[32];
    __shared__ int s_carry;
    int tid = threadIdx.x, lane = tid & 31, wid = tid >> 5;
    if (tid == 0) s_carry = 0;
    __syncthreads();
    for (int base = 0; base < NN; base += 1024){
        int i = base + tid;
        int v = (i < NN) ? g_deg[i] : 0;
        int x = v;
        #pragma unroll
        for (int d = 1; d < 32; d <<= 1){
            int t = __shfl_up_sync(0xffffffffu, x, d);
            if (lane >= d) x += t;
        }
        if (lane == 31) wsum[wid] = x;
        __syncthreads();
        if (wid == 0){
            int y = wsum[lane];
            #pragma unroll
            for (int d = 1; d < 32; d <<= 1){
                int t = __shfl_up_sync(0xffffffffu, y, d);
                if (lane >= d) y += t;
            }
            wsum[lane] = y;
        }
        __syncthreads();
        int woff = (wid == 0) ? 0 : wsum[wid-1];
        int excl = x - v + woff + s_carry;
        if (i < NN){ g_off[i] = excl; g_cur[i] = excl; }
        int btot = wsum[31];
        __syncthreads();
        if (tid == 0) s_carry += btot;
        __syncthreads();
    }
    if (tid == 0) g_off[NN] = s_carry;
}

__global__ void k_scatter(const int* __restrict__ ei, const float* __restrict__ ew){
    int e = blockIdx.x*blockDim.x + threadIdx.x;
    if (e < NE){
        int d = ei[NE + e];
        int p = atomicAdd(&g_cur[d], 1);
        g_csr[p] = make_float2(__int_as_float(ei[e]), ew[e]);
    }
}

// aggregation: u = h + segment_sum(h[src]*w)
// one warp per node; lane covers 2 feature columns (float2)  (R2 version — proven)
__global__ void k_agg(){
    int node = blockIdx.x*8 + (threadIdx.x >> 5);
    int lane = threadIdx.x & 31;
    if (node >= NN) return;
    float2 acc = *(const float2*)&g_h[node*EMB + lane*2];
    int s = g_off[node], e = g_off[node+1];
    for (int p = s; p < e; p++){
        float2 m = g_csr[p];
        int src = __float_as_int(m.x);
        float w = m.y;
        float2 hv = *(const float2*)&g_h[src*EMB + lane*2];
        acc.x = fmaf(hv.x, w, acc.x);
        acc.y = fmaf(hv.y, w, acc.y);
    }
    *(float2*)&g_u[node*EMB + lane*2] = acc;
}

// MODE 0: encoder (no stats). MODE 1: gemm1 (stats out -> [l][0]).
// MODE 2: gemm2 (BN-ReLU in from [l][0], stats out -> [l][1]).
template<int MODE>
__global__ void __launch_bounds__(128, 2) k_gemm(const float* __restrict__ Xext,
                                                 const float* __restrict__ W,
                                                 const float* __restrict__ B,
                                                 int layer,
                                                 const float* __restrict__ gamma,
                                                 const float* __restrict__ beta){
    __shared__ float xs[EMB][128];
    __shared__ float ws[EMB][EMB];
    __shared__ __align__(16) float sA[EMB], sC[EMB];
    int tid  = threadIdx.x;
    int row0 = blockIdx.x * 128;
    const float* X = (MODE == 0) ? Xext : (MODE == 1 ? g_u : g_t1);
    float*       Y = (MODE == 0) ? g_h  : (MODE == 1 ? g_t1 : g_t2);
    float* statsOut = (MODE == 1) ? g_stats[layer][0] : g_stats[layer][1];

    if (MODE == 2){
        const float* si = g_stats[layer][0];
        if (tid < EMB){
            float mean = si[tid] * (1.0f/NN);
            float var  = si[EMB + tid] * (1.0f/NN) - mean*mean;
            float a = gamma[tid] * rsqrtf(var + BN_EPS);
            sA[tid] = a;
            sC[tid] = beta[tid] - mean*a;
        }
        __syncthreads();
    }

    {
        const float4* w4 = (const float4*)W;
        float4* s4 = (float4*)ws;
        #pragma unroll
        for (int i = 0; i < 8; i++) s4[tid + i*128] = w4[tid + i*128];
    }
    {
        int grow = row0 + tid;
        #pragma unroll
        for (int k4 = 0; k4 < 16; k4++){
            float4 v = make_float4(0.f, 0.f, 0.f, 0.f);
            if (grow < NN) v = *(const float4*)&X[grow*EMB + k4*4];
            if (MODE == 2){
                float4 a = *(const float4*)&sA[k4*4];
                float4 c = *(const float4*)&sC[k4*4];
                v.x = fmaxf(fmaf(v.x, a.x, c.x), 0.f);
                v.y = fmaxf(fmaf(v.y, a.y, c.y), 0.f);
                v.z = fmaxf(fmaf(v.z, a.z, c.z), 0.f);
                v.w = fmaxf(fmaf(v.w, a.w, c.w), 0.f);
            }
            xs[k4*4+0][tid] = v.x; xs[k4*4+1][tid] = v.y;
            xs[k4*4+2][tid] = v.z; xs[k4*4+3][tid] = v.w;
        }
    }
    __syncthreads();

    int tc = tid & 7;
    int tr = tid >> 3;
    ull acc[8][4];
    #pragma unroll
    for (int i = 0; i < 8; i++)
        #pragma unroll
        for (int j = 0; j < 4; j++) acc[i][j] = 0ULL;

    #pragma unroll 4
    for (int k = 0; k < EMB; k++){
        float4 xlo = *(const float4*)&xs[k][tr*8];
        float4 xhi = *(const float4*)&xs[k][tr*8 + 4];
        float4 wlo = *(const float4*)&ws[k][tc*8];
        float4 whi = *(const float4*)&ws[k][tc*8 + 4];
        ull w01 = pack2(wlo.x, wlo.y), w23 = pack2(wlo.z, wlo.w);
        ull w45 = pack2(whi.x, whi.y), w67 = pack2(whi.z, whi.w);
        float xv[8] = {xlo.x, xlo.y, xlo.z, xlo.w, xhi.x, xhi.y, xhi.z, xhi.w};
        #pragma unroll
        for (int i = 0; i < 8; i++){
            ull xp = pack2(xv[i], xv[i]);
            ffma2(acc[i][0], xp, w01);
            ffma2(acc[i][1], xp, w23);
            ffma2(acc[i][2], xp, w45);
            ffma2(acc[i][3], xp, w67);
        }
    }
    __syncthreads();

    float bias[8];
    {
        float4 blo = *(const float4*)&B[tc*8];
        float4 bhi = *(const float4*)&B[tc*8 + 4];
        bias[0]=blo.x; bias[1]=blo.y; bias[2]=blo.z; bias[3]=blo.w;
        bias[4]=bhi.x; bias[5]=bhi.y; bias[6]=bhi.z; bias[7]=bhi.w;
    }
    float bsum[8], bss[8];
    #pragma unroll
    for (int j = 0; j < 8; j++){ bsum[j] = 0.f; bss[j] = 0.f; }

    #pragma unroll
    for (int i = 0; i < 8; i++){
        int row = row0 + tr*8 + i;
        if (row < NN){
            float y[8];
            #pragma unroll
            for (int j = 0; j < 4; j++){
                float2 p = unpack2(acc[i][j]);
                y[2*j]   = p.x + bias[2*j];
                y[2*j+1] = p.y + bias[2*j+1];
            }
            *(float4*)&Y[row*EMB + tc*8]     = make_float4(y[0], y[1], y[2], y[3]);
            *(float4*)&Y[row*EMB + tc*8 + 4] = make_float4(y[4], y[5], y[6], y[7]);
            if (MODE >= 1){
                #pragma unroll
                for (int j = 0; j < 8; j++){
                    bsum[j] += y[j];
                    bss[j]  = fmaf(y[j], y[j], bss[j]);
                }
            }
        }
    }
    if (MODE >= 1){
        float* red  = &ws[0][0];
        float* red2 = red + 1024;
        #pragma unroll
        for (int j = 0; j < 8; j++){
            red [tr*64 + tc*8 + j] = bsum[j];
            red2[tr*64 + tc*8 + j] = bss[j];
        }
        __syncthreads();
        if (tid < 64){
            float s = 0.f;
            #pragma unroll
            for (int t = 0; t < 16; t++) s += red[t*64 + tid];
            atomicAdd(&statsOut[tid], s);
        } else {
            int c = tid - 64;
            float s = 0.f;
            #pragma unroll
            for (int t = 0; t < 16; t++) s += red2[t*64 + c];
            atomicAdd(&statsOut[EMB + c], s);
        }
    }
}

__global__ void k_resid(int layer,
                        const float* __restrict__ gamma,
                        const float* __restrict__ beta,
                        float* __restrict__ outp){
    __shared__ __align__(16) float sA[EMB], sC[EMB];
    int tid = threadIdx.x;
    const float* si = g_stats[layer][1];
    if (tid < EMB){
        float mean = si[tid] * (1.0f/NN);
        float var  = si[EMB + tid] * (1.0f/NN) - mean*mean;
        float a = gamma[tid] * rsqrtf(var + BN_EPS);
        sA[tid] = a;
        sC[tid] = beta[tid] - mean*a;
    }
    __syncthreads();
    int i = blockIdx.x*blockDim.x + tid;
    if (i < NN*16){
        int c4 = (i & 15) * 4;
        float4 a = *(const float4*)&sA[c4];
        float4 c = *(const float4*)&sC[c4];
        float4 t = ((const float4*)g_t2)[i];
        float4 h = ((const float4*)g_h)[i];
        float4 r;
        r.x = fmaxf(fmaf(t.x, a.x, c.x), 0.f) + h.x;
        r.y = fmaxf(fmaf(t.y, a.y, c.y), 0.f) + h.y;
        r.z = fmaxf(fmaf(t.z, a.z, c.z), 0.f) + h.z;
        r.w = fmaxf(fmaf(t.w, a.w, c.w), 0.f) + h.w;
        float4* dst = outp ? (float4*)outp : (float4*)g_h;
        dst[i] = r;
    }
}

extern "C" void kernel_launch(void* const* d_in, const int* in_sizes, int n_in,
                              void* d_out, int out_size){
    const float* x   = (const float*)d_in[0];
    const int*   ei  = (const int*)  d_in[1];
    const float* ew  = (const float*)d_in[3];
    const float* aew = (const float*)d_in[4];
    const float* aeb = (const float*)d_in[5];
    const float* W1  = (const float*)d_in[6];
    const float* b1  = (const float*)d_in[7];
    const float* g1  = (const float*)d_in[8];
    const float* be1 = (const float*)d_in[9];
    const float* W2  = (const float*)d_in[10];
    const float* b2  = (const float*)d_in[11];
    const float* go  = (const float*)d_in[12];
    const float* beo = (const float*)d_in[13];
    float* out = (float*)d_out;

    k_init   <<<(NN + 255)/256, 256>>>();
    k_hist   <<<(NE + 255)/256, 256>>>(ei);
    k_scan   <<<1, 1024>>>();
    k_scatter<<<(NE + 255)/256, 256>>>(ei, ew);

    int gb = (NN + 127)/128;
    k_gemm<0><<<gb, 128>>>(x, aew, aeb, 0, nullptr, nullptr);

    for (int l = 0; l < NL; l++){
        k_agg    <<<(NN + 7)/8, 256>>>();
        k_gemm<1><<<gb, 128>>>(nullptr, W1 + l*EMB*EMB, b1 + l*EMB, l, nullptr, nullptr);
        k_gemm<2><<<gb, 128>>>(nullptr, W2 + l*EMB*EMB, b2 + l*EMB, l, g1 + l*EMB, be1 + l*EMB);
        k_resid  <<<(NN*16 + 255)/256, 256>>>(l, go + l*EMB, beo + l*EMB,
                                              l == NL-1 ? out : nullptr);
    }
}

// round 10
// speedup vs baseline: 1.1462x; 1.1462x over previous
#include <cuda_runtime.h>

#define NN 50000
#define NE 800000
#define EMB 64
#define NL 4
#define BN_EPS 1e-5f
#define NBLK 148
#define NTHR 1024

typedef unsigned long long ull;

// ---------------- device scratch ----------------
__device__ float  g_h [NN*EMB];
__device__ float  g_u [NN*EMB];
__device__ float  g_t1[NN*EMB];
__device__ float  g_t2[NN*EMB];
__device__ int    g_deg[NN];
__device__ int    g_off[NN+1];
__device__ int    g_cur[NN];
__device__ float2 g_csr[NE];
__device__ float  g_stats[NL][2][2*EMB];   // [layer][stage][sum(64)|ss(64)]
__device__ unsigned g_barcnt;              // stays 0 between launches (self-resetting)
__device__ unsigned g_barphase;            // monotonic across launches; base read at start

// shared memory layout (dynamic)
#define SM_XS    0                         // 64*128 floats = 32768 B
#define SM_WS    32768                     // 64*68  floats = 17408 B
#define SM_SRED  (32768+17408)             // 128 floats = 512 B
#define SM_SBN   (SM_SRED+512)             // 128 floats = 512 B
#define SM_SCAN  (SM_SBN+512)              // 34 ints
#define SMEM_BYTES (SM_SCAN + 160)

__device__ __forceinline__ ull pack2(float a, float b){
    ull r; asm("mov.b64 %0, {%1, %2};" : "=l"(r) : "f"(a), "f"(b)); return r;
}
__device__ __forceinline__ float2 unpack2(ull v){
    float2 r; asm("mov.b64 {%0, %1}, %2;" : "=f"(r.x), "=f"(r.y) : "l"(v)); return r;
}
__device__ __forceinline__ void ffma2(ull &d, ull a, ull b){
    asm("fma.rn.f32x2 %0, %1, %2, %0;" : "+l"(d) : "l"(a), "l"(b));
}

// ---------------- grid-wide barrier (sense via monotonic phase) ----------------
__device__ __forceinline__ void grid_bar(unsigned barBase, unsigned &barN){
    __syncthreads();
    barN++;
    if (threadIdx.x == 0){
        __threadfence();
        if (atomicAdd(&g_barcnt, 1u) == gridDim.x - 1u){
            g_barcnt = 0u;                 // all arrived; safe before release
            __threadfence();
            atomicExch(&g_barphase, barBase + barN);
        } else {
            while (atomicAdd(&g_barphase, 0u) < barBase + barN) __nanosleep(64);
        }
        __threadfence();
    }
    __syncthreads();
}

// ---------------- GEMM phase: Y[NN,64] = op(X)[NN,64] @ W[64,64] + B ----------------
// tiles of 128 rows; 1024 threads; thread-tile 2 rows x 4 cols (f32x2).
// doBN: X transformed by relu(X*a+c) with coeffs from bnStats/gamma/beta.
// doStats: column sum/sumsq of Y accumulated into statsOut (global atomics).
__device__ __noinline__ void gemm_phase(const float* __restrict__ X,
                                        float* __restrict__ Y,
                                        const float* __restrict__ W,
                                        const float* __restrict__ B,
                                        float* statsOut,
                                        const float* bnStats,
                                        const float* __restrict__ gamma,
                                        const float* __restrict__ beta,
                                        char* smem, int doStats, int doBN)
{
    float* XS   = (float*)(smem + SM_XS);     // [k][row] 64 x 128
    float* WS   = (float*)(smem + SM_WS);     // [k][j]   64 x 68 (padded)
    float* SRED = (float*)(smem + SM_SRED);   // 128
    float* SBN  = (float*)(smem + SM_SBN);    // a[64] | c[64]
    int tid = threadIdx.x;

    if (doBN && tid < EMB){
        float mean = bnStats[tid] * (1.0f/NN);
        float var  = bnStats[EMB + tid] * (1.0f/NN) - mean*mean;
        float a = gamma[tid] * rsqrtf(var + BN_EPS);
        SBN[tid] = a;
        SBN[EMB + tid] = beta[tid] - mean*a;
    }
    if (doStats && tid < 128) SRED[tid] = 0.f;
    {   // load W (4096 floats) into padded shared
        float4 v = ((const float4*)W)[tid];
        int k = tid >> 4, j4 = (tid & 15) << 2;
        *(float4*)&WS[k*68 + j4] = v;
    }
    __syncthreads();

    const int lrow = tid & 127;       // loader row within tile
    const int lkq  = tid >> 7;        // loader k-octant (8 k's each)
    const int rg   = tid >> 4;        // 0..63 -> rows rg*2, rg*2+1
    const int cg   = tid & 15;        // cols cg*4 .. cg*4+3
    float4 bias4 = *(const float4*)&B[cg*4];
    float bsum0=0.f,bsum1=0.f,bsum2=0.f,bsum3=0.f;
    float bss0=0.f,bss1=0.f,bss2=0.f,bss3=0.f;

    const int ntiles = (NN + 127) >> 7;    // 391
    for (int t = blockIdx.x; t < ntiles; t += gridDim.x){
        int row0 = t << 7;
        // ---- load X tile (transposed, optional BN-ReLU) ----
        {
            int grow = row0 + lrow;
            #pragma unroll
            for (int j = 0; j < 2; j++){
                int k = lkq*8 + j*4;
                float4 v = make_float4(0.f,0.f,0.f,0.f);
                if (grow < NN) v = *(const float4*)&X[grow*EMB + k];
                if (doBN){
                    float4 a = *(const float4*)&SBN[k];
                    float4 c = *(const float4*)&SBN[EMB + k];
                    v.x = fmaxf(fmaf(v.x,a.x,c.x),0.f);
                    v.y = fmaxf(fmaf(v.y,a.y,c.y),0.f);
                    v.z = fmaxf(fmaf(v.z,a.z,c.z),0.f);
                    v.w = fmaxf(fmaf(v.w,a.w,c.w),0.f);
                }
                XS[(k+0)*128+lrow]=v.x; XS[(k+1)*128+lrow]=v.y;
                XS[(k+2)*128+lrow]=v.z; XS[(k+3)*128+lrow]=v.w;
            }
        }
        __syncthreads();
        // ---- compute 2x4 ----
        ull a00=0ULL,a01=0ULL,a10=0ULL,a11=0ULL;
        #pragma unroll 8
        for (int k = 0; k < EMB; k++){
            float2 xv = *(const float2*)&XS[k*128 + rg*2];
            float4 wv = *(const float4*)&WS[k*68 + cg*4];
            ull w01 = pack2(wv.x, wv.y), w23 = pack2(wv.z, wv.w);
            ull x0 = pack2(xv.x, xv.x), x1 = pack2(xv.y, xv.y);
            ffma2(a00, x0, w01); ffma2(a01, x0, w23);
            ffma2(a10, x1, w01); ffma2(a11, x1, w23);
        }
        // ---- epilogue ----
        {
            int row = row0 + rg*2;
            if (row < NN){
                float2 p0 = unpack2(a00), p1 = unpack2(a01);
                float y0=p0.x+bias4.x, y1=p0.y+bias4.y, y2=p1.x+bias4.z, y3=p1.y+bias4.w;
                *(float4*)&Y[row*EMB + cg*4] = make_float4(y0,y1,y2,y3);
                if (doStats){
                    bsum0+=y0; bss0=fmaf(y0,y0,bss0);
                    bsum1+=y1; bss1=fmaf(y1,y1,bss1);
                    bsum2+=y2; bss2=fmaf(y2,y2,bss2);
                    bsum3+=y3; bss3=fmaf(y3,y3,bss3);
                }
            }
            row++;
            if (row < NN){
                float2 p0 = unpack2(a10), p1 = unpack2(a11);
                float y0=p0.x+bias4.x, y1=p0.y+bias4.y, y2=p1.x+bias4.z, y3=p1.y+bias4.w;
                *(float4*)&Y[row*EMB + cg*4] = make_float4(y0,y1,y2,y3);
                if (doStats){
                    bsum0+=y0; bss0=fmaf(y0,y0,bss0);
                    bsum1+=y1; bss1=fmaf(y1,y1,bss1);
                    bsum2+=y2; bss2=fmaf(y2,y2,bss2);
                    bsum3+=y3; bss3=fmaf(y3,y3,bss3);
                }
            }
        }
        __syncthreads();   // XS reused next tile
    }

    if (doStats){
        bsum0 += __shfl_xor_sync(0xffffffffu, bsum0, 16);
        bsum1 += __shfl_xor_sync(0xffffffffu, bsum1, 16);
        bsum2 += __shfl_xor_sync(0xffffffffu, bsum2, 16);
        bsum3 += __shfl_xor_sync(0xffffffffu, bsum3, 16);
        bss0  += __shfl_xor_sync(0xffffffffu, bss0, 16);
        bss1  += __shfl_xor_sync(0xffffffffu, bss1, 16);
        bss2  += __shfl_xor_sync(0xffffffffu, bss2, 16);
        bss3  += __shfl_xor_sync(0xffffffffu, bss3, 16);
        if ((tid & 16) == 0){
            atomicAdd(&SRED[cg*4+0], bsum0);
            atomicAdd(&SRED[cg*4+1], bsum1);
            atomicAdd(&SRED[cg*4+2], bsum2);
            atomicAdd(&SRED[cg*4+3], bsum3);
            atomicAdd(&SRED[EMB+cg*4+0], bss0);
            atomicAdd(&SRED[EMB+cg*4+1], bss1);
            atomicAdd(&SRED[EMB+cg*4+2], bss2);
            atomicAdd(&SRED[EMB+cg*4+3], bss3);
        }
        __syncthreads();
        if (tid < 128) atomicAdd(&statsOut[tid], SRED[tid]);
    }
}

// ---------------- residual phase: dst = relu(bn(t2)) + h ----------------
__device__ __noinline__ void resid_phase(const float* bnStats,
                                         const float* __restrict__ gamma,
                                         const float* __restrict__ beta,
                                         float* __restrict__ dstp,
                                         char* smem)
{
    float* SBN = (float*)(smem + SM_SBN);
    int tid = threadIdx.x;
    if (tid < EMB){
        float mean = bnStats[tid] * (1.0f/NN);
        float var  = bnStats[EMB + tid] * (1.0f/NN) - mean*mean;
        float a = gamma[tid] * rsqrtf(var + BN_EPS);
        SBN[tid] = a;
        SBN[EMB + tid] = beta[tid] - mean*a;
    }
    __syncthreads();
    float4* dst = (float4*)dstp;
    for (int i = blockIdx.x*NTHR + tid; i < NN*16; i += gridDim.x*NTHR){
        int c4 = (i & 15) * 4;
        float4 a = *(const float4*)&SBN[c4];
        float4 c = *(const float4*)&SBN[EMB + c4];
        float4 t = ((const float4*)g_t2)[i];
        float4 h = ((const float4*)g_h)[i];
        float4 r;
        r.x = fmaxf(fmaf(t.x,a.x,c.x),0.f) + h.x;
        r.y = fmaxf(fmaf(t.y,a.y,c.y),0.f) + h.y;
        r.z = fmaxf(fmaf(t.z,a.z,c.z),0.f) + h.z;
        r.w = fmaxf(fmaf(t.w,a.w,c.w),0.f) + h.w;
        dst[i] = r;
    }
    __syncthreads();
}

// ---------------- aggregation phase: u = h + segsum(h[src]*w) ----------------
__device__ __noinline__ void agg_phase()
{
    int gw   = (blockIdx.x*NTHR + threadIdx.x) >> 5;
    int lane = threadIdx.x & 31;
    const int nwarps = (NBLK*NTHR) >> 5;     // 4736
    for (int node = gw; node < NN; node += nwarps){
        float2 acc = *(const float2*)&g_h[node*EMB + lane*2];
        int s = g_off[node], e = g_off[node+1];
        for (int p = s; p < e; p++){
            float2 m = g_csr[p];
            int src = __float_as_int(m.x);
            float w = m.y;
            float2 hv = *(const float2*)&g_h[src*EMB + lane*2];
            acc.x = fmaf(hv.x, w, acc.x);
            acc.y = fmaf(hv.y, w, acc.y);
        }
        *(float2*)&g_u[node*EMB + lane*2] = acc;
    }
}

// ---------------- the megakernel ----------------
__global__ void __launch_bounds__(NTHR, 1) k_all(
    const float* __restrict__ x,   const int* __restrict__ ei,
    const float* __restrict__ ew,
    const float* __restrict__ aew, const float* __restrict__ aeb,
    const float* __restrict__ W1,  const float* __restrict__ b1,
    const float* __restrict__ g1,  const float* __restrict__ be1,
    const float* __restrict__ W2,  const float* __restrict__ b2,
    const float* __restrict__ go,  const float* __restrict__ beo,
    float* __restrict__ out)
{
    extern __shared__ __align__(16) char smem[];
    int tid = threadIdx.x, bid = blockIdx.x;
    const int gs = NBLK * NTHR;

    // read barrier base (before any block can flip it)
    unsigned* SBp = (unsigned*)(smem + SM_SCAN + 144);
    if (tid == 0) *SBp = atomicAdd(&g_barphase, 0u);
    __syncthreads();
    unsigned barBase = *SBp;
    unsigned barN = 0;

    // phase: init
    for (int i = bid*NTHR + tid; i < NN; i += gs) g_deg[i] = 0;
    if (bid == 0) ((float*)g_stats)[tid] = 0.f;   // NL*2*128 = 1024 = NTHR
    grid_bar(barBase, barN);

    // phase: histogram
    for (int e = bid*NTHR + tid; e < NE; e += gs)
        atomicAdd(&g_deg[ei[NE + e]], 1);
    grid_bar(barBase, barN);

    // phase: scan (block 0 only, coalesced block-strided)
    if (bid == 0){
        int* wsum = (int*)(smem + SM_SCAN);
        int* s_carry = wsum + 32;
        int lane = tid & 31, wid = tid >> 5;
        if (tid == 0) *s_carry = 0;
        __syncthreads();
        for (int base = 0; base < NN; base += NTHR){
            int i = base + tid;
            int v = (i < NN) ? g_deg[i] : 0;
            int xP = v;
            #pragma unroll
            for (int d = 1; d < 32; d <<= 1){
                int t = __shfl_up_sync(0xffffffffu, xP, d);
                if (lane >= d) xP += t;
            }
            if (lane == 31) wsum[wid] = xP;
            __syncthreads();
            if (wid == 0){
                int y = wsum[lane];
                #pragma unroll
                for (int d = 1; d < 32; d <<= 1){
                    int t = __shfl_up_sync(0xffffffffu, y, d);
                    if (lane >= d) y += t;
                }
                wsum[lane] = y;
            }
            __syncthreads();
            int woff = (wid == 0) ? 0 : wsum[wid-1];
            int excl = xP - v + woff + *s_carry;
            if (i < NN){ g_off[i] = excl; g_cur[i] = excl; }
            int btot = wsum[31];
            __syncthreads();
            if (tid == 0) *s_carry += btot;
            __syncthreads();
        }
        if (tid == 0) g_off[NN] = *s_carry;
    }
    grid_bar(barBase, barN);

    // phase: scatter
    for (int e = bid*NTHR + tid; e < NE; e += gs){
        int d = ei[NE + e];
        int p = atomicAdd(&g_cur[d], 1);
        g_csr[p] = make_float2(__int_as_float(ei[e]), ew[e]);
    }
    grid_bar(barBase, barN);

    // phase: atom encoder GEMM
    gemm_phase(x, g_h, aew, aeb, nullptr, nullptr, nullptr, nullptr, smem, 0, 0);
    grid_bar(barBase, barN);

    for (int l = 0; l < NL; l++){
        agg_phase();
        grid_bar(barBase, barN);

        gemm_phase(g_u, g_t1, W1 + l*EMB*EMB, b1 + l*EMB,
                   &g_stats[l][0][0], nullptr, nullptr, nullptr, smem, 1, 0);
        grid_bar(barBase, barN);

        gemm_phase(g_t1, g_t2, W2 + l*EMB*EMB, b2 + l*EMB,
                   &g_stats[l][1][0], &g_stats[l][0][0],
                   g1 + l*EMB, be1 + l*EMB, smem, 1, 1);
        grid_bar(barBase, barN);

        resid_phase(&g_stats[l][1][0], go + l*EMB, beo + l*EMB,
                    (l == NL-1) ? out : g_h, smem);
        grid_bar(barBase, barN);
    }
}

// ---------------- driver ----------------
extern "C" void kernel_launch(void* const* d_in, const int* in_sizes, int n_in,
                              void* d_out, int out_size){
    const float* x   = (const float*)d_in[0];
    const int*   ei  = (const int*)  d_in[1];
    // d_in[2] = edge_attr (unused)
    const float* ew  = (const float*)d_in[3];
    const float* aew = (const float*)d_in[4];
    const float* aeb = (const float*)d_in[5];
    const float* W1  = (const float*)d_in[6];
    const float* b1  = (const float*)d_in[7];
    const float* g1  = (const float*)d_in[8];
    const float* be1 = (const float*)d_in[9];
    const float* W2  = (const float*)d_in[10];
    const float* b2  = (const float*)d_in[11];
    const float* go  = (const float*)d_in[12];
    const float* beo = (const float*)d_in[13];
    float* out = (float*)d_out;

    cudaFuncSetAttribute(k_all, cudaFuncAttributeMaxDynamicSharedMemorySize, SMEM_BYTES);
    k_all<<<NBLK, NTHR, SMEM_BYTES>>>(x, ei, ew, aew, aeb,
                                      W1, b1, g1, be1, W2, b2, go, beo, out);
}

// round 14
// speedup vs baseline: 1.5019x; 1.3103x over previous
#include <cuda_runtime.h>

#define NN 50000
#define NE 800000
#define EMB 64
#define NL 4
#define BN_EPS 1e-5f

typedef unsigned long long ull;

__device__ float  g_h [NN*EMB];
__device__ float  g_u [NN*EMB];
__device__ float  g_t1[NN*EMB];
__device__ float  g_t2[NN*EMB];
__device__ int    g_deg[NN];
__device__ int    g_off[NN+1];
__device__ int    g_cur[NN];
__device__ float2 g_csr[NE];
__device__ float  g_stats[NL][2][2*EMB];   // [layer][stage][sum|ss]

__device__ __forceinline__ ull pack2(float a, float b){
    ull r; asm("mov.b64 %0, {%1, %2};" : "=l"(r) : "f"(a), "f"(b)); return r;
}
__device__ __forceinline__ float2 unpack2(ull v){
    float2 r; asm("mov.b64 {%0, %1}, %2;" : "=f"(r.x), "=f"(r.y) : "l"(v)); return r;
}
__device__ __forceinline__ void ffma2(ull &d, ull a, ull b){
    asm("fma.rn.f32x2 %0, %1, %2, %0;" : "+l"(d) : "l"(a), "l"(b));
}

__global__ void k_init(){
    int i = blockIdx.x*blockDim.x + threadIdx.x;
    if (i < NN) g_deg[i] = 0;
    if (i < NL*2*2*EMB) ((float*)g_stats)[i] = 0.f;
}

__global__ void k_hist(const int* __restrict__ ei){
    int e = blockIdx.x*blockDim.x + threadIdx.x;
    if (e < NE) atomicAdd(&g_deg[ei[NE + e]], 1);
}

// coalesced block-strided scan (R2 version — proven)
__global__ void k_scan(){
    __shared__ int wsum[32];
    __shared__ int s_carry;
    int tid = threadIdx.x, lane = tid & 31, wid = tid >> 5;
    if (tid == 0) s_carry = 0;
    __syncthreads();
    for (int base = 0; base < NN; base += 1024){
        int i = base + tid;
        int v = (i < NN) ? g_deg[i] : 0;
        int x = v;
        #pragma unroll
        for (int d = 1; d < 32; d <<= 1){
            int t = __shfl_up_sync(0xffffffffu, x, d);
            if (lane >= d) x += t;
        }
        if (lane == 31) wsum[wid] = x;
        __syncthreads();
        if (wid == 0){
            int y = wsum[lane];
            #pragma unroll
            for (int d = 1; d < 32; d <<= 1){
                int t = __shfl_up_sync(0xffffffffu, y, d);
                if (lane >= d) y += t;
            }
            wsum[lane] = y;
        }
        __syncthreads();
        int woff = (wid == 0) ? 0 : wsum[wid-1];
        int excl = x - v + woff + s_carry;
        if (i < NN){ g_off[i] = excl; g_cur[i] = excl; }
        int btot = wsum[31];
        __syncthreads();
        if (tid == 0) s_carry += btot;
        __syncthreads();
    }
    if (tid == 0) g_off[NN] = s_carry;
}

__global__ void k_scatter(const int* __restrict__ ei, const float* __restrict__ ew){
    int e = blockIdx.x*blockDim.x + threadIdx.x;
    if (e < NE){
        int d = ei[NE + e];
        int p = atomicAdd(&g_cur[d], 1);
        g_csr[p] = make_float2(__int_as_float(ei[e]), ew[e]);
    }
}

// aggregation: u = h + segment_sum(h[src]*w)
// one warp per node; lane covers 2 feature columns (float2); __ldg + unroll for MLP
__global__ void k_agg(){
    int node = blockIdx.x*8 + (threadIdx.x >> 5);
    int lane = threadIdx.x & 31;
    if (node >= NN) return;
    const float2* __restrict__ H2 = (const float2*)g_h;
    float2 acc = __ldg(&H2[node*32 + lane]);
    int s = g_off[node], e = g_off[node+1];
    #pragma unroll 4
    for (int p = s; p < e; p++){
        float2 m = __ldg(&g_csr[p]);
        int src = __float_as_int(m.x);
        float w = m.y;
        float2 hv = __ldg(&H2[src*32 + lane]);
        acc.x = fmaf(hv.x, w, acc.x);
        acc.y = fmaf(hv.y, w, acc.y);
    }
    *(float2*)&g_u[node*EMB + lane*2] = acc;
}

// MODE 0: encoder (no stats). MODE 1: gemm1 (stats out -> [l][0]).
// MODE 2: gemm2 (BN-ReLU in from [l][0], stats out -> [l][1]).
template<int MODE>
__global__ void __launch_bounds__(128, 2) k_gemm(const float* __restrict__ Xext,
                                                 const float* __restrict__ W,
                                                 const float* __restrict__ B,
                                                 int layer,
                                                 const float* __restrict__ gamma,
                                                 const float* __restrict__ beta){
    __shared__ float xs[EMB][128];
    __shared__ float ws[EMB][EMB];
    __shared__ __align__(16) float sA[EMB], sC[EMB];
    int tid  = threadIdx.x;
    int row0 = blockIdx.x * 128;
    const float* X = (MODE == 0) ? Xext : (MODE == 1 ? g_u : g_t1);
    float*       Y = (MODE == 0) ? g_h  : (MODE == 1 ? g_t1 : g_t2);
    float* statsOut = (MODE == 1) ? g_stats[layer][0] : g_stats[layer][1];

    if (MODE == 2){
        const float* si = g_stats[layer][0];
        if (tid < EMB){
            float mean = si[tid] * (1.0f/NN);
            float var  = si[EMB + tid] * (1.0f/NN) - mean*mean;
            float a = gamma[tid] * rsqrtf(var + BN_EPS);
            sA[tid] = a;
            sC[tid] = beta[tid] - mean*a;
        }
        __syncthreads();
    }

    {
        const float4* w4 = (const float4*)W;
        float4* s4 = (float4*)ws;
        #pragma unroll
        for (int i = 0; i < 8; i++) s4[tid + i*128] = w4[tid + i*128];
    }
    {
        int grow = row0 + tid;
        #pragma unroll
        for (int k4 = 0; k4 < 16; k4++){
            float4 v = make_float4(0.f, 0.f, 0.f, 0.f);
            if (grow < NN) v = *(const float4*)&X[grow*EMB + k4*4];
            if (MODE == 2){
                float4 a = *(const float4*)&sA[k4*4];
                float4 c = *(const float4*)&sC[k4*4];
                v.x = fmaxf(fmaf(v.x, a.x, c.x), 0.f);
                v.y = fmaxf(fmaf(v.y, a.y, c.y), 0.f);
                v.z = fmaxf(fmaf(v.z, a.z, c.z), 0.f);
                v.w = fmaxf(fmaf(v.w, a.w, c.w), 0.f);
            }
            xs[k4*4+0][tid] = v.x; xs[k4*4+1][tid] = v.y;
            xs[k4*4+2][tid] = v.z; xs[k4*4+3][tid] = v.w;
        }
    }
    __syncthreads();

    int tc = tid & 7;
    int tr = tid >> 3;
    ull acc[8][4];
    #pragma unroll
    for (int i = 0; i < 8; i++)
        #pragma unroll
        for (int j = 0; j < 4; j++) acc[i][j] = 0ULL;

    #pragma unroll 4
    for (int k = 0; k < EMB; k++){
        float4 xlo = *(const float4*)&xs[k][tr*8];
        float4 xhi = *(const float4*)&xs[k][tr*8 + 4];
        float4 wlo = *(const float4*)&ws[k][tc*8];
        float4 whi = *(const float4*)&ws[k][tc*8 + 4];
        ull w01 = pack2(wlo.x, wlo.y), w23 = pack2(wlo.z, wlo.w);
        ull w45 = pack2(whi.x, whi.y), w67 = pack2(whi.z, whi.w);
        float xv[8] = {xlo.x, xlo.y, xlo.z, xlo.w, xhi.x, xhi.y, xhi.z, xhi.w};
        #pragma unroll
        for (int i = 0; i < 8; i++){
            ull xp = pack2(xv[i], xv[i]);
            ffma2(acc[i][0], xp, w01);
            ffma2(acc[i][1], xp, w23);
            ffma2(acc[i][2], xp, w45);
            ffma2(acc[i][3], xp, w67);
        }
    }
    __syncthreads();

    float bias[8];
    {
        float4 blo = *(const float4*)&B[tc*8];
        float4 bhi = *(const float4*)&B[tc*8 + 4];
        bias[0]=blo.x; bias[1]=blo.y; bias[2]=blo.z; bias[3]=blo.w;
        bias[4]=bhi.x; bias[5]=bhi.y; bias[6]=bhi.z; bias[7]=bhi.w;
    }
    float bsum[8], bss[8];
    #pragma unroll
    for (int j = 0; j < 8; j++){ bsum[j] = 0.f; bss[j] = 0.f; }

    #pragma unroll
    for (int i = 0; i < 8; i++){
        int row = row0 + tr*8 + i;
        if (row < NN){
            float y[8];
            #pragma unroll
            for (int j = 0; j < 4; j++){
                float2 p = unpack2(acc[i][j]);
                y[2*j]   = p.x + bias[2*j];
                y[2*j+1] = p.y + bias[2*j+1];
            }
            *(float4*)&Y[row*EMB + tc*8]     = make_float4(y[0], y[1], y[2], y[3]);
            *(float4*)&Y[row*EMB + tc*8 + 4] = make_float4(y[4], y[5], y[6], y[7]);
            if (MODE >= 1){
                #pragma unroll
                for (int j = 0; j < 8; j++){
                    bsum[j] += y[j];
                    bss[j]  = fmaf(y[j], y[j], bss[j]);
                }
            }
        }
    }
    if (MODE >= 1){
        float* red  = &ws[0][0];
        float* red2 = red + 1024;
        #pragma unroll
        for (int j = 0; j < 8; j++){
            red [tr*64 + tc*8 + j] = bsum[j];
            red2[tr*64 + tc*8 + j] = bss[j];
        }
        __syncthreads();
        if (tid < 64){
            float s = 0.f;
            #pragma unroll
            for (int t = 0; t < 16; t++) s += red[t*64 + tid];
            atomicAdd(&statsOut[tid], s);
        } else {
            int c = tid - 64;
            float s = 0.f;
            #pragma unroll
            for (int t = 0; t < 16; t++) s += red2[t*64 + c];
            atomicAdd(&statsOut[EMB + c], s);
        }
    }
}

__global__ void k_resid(int layer,
                        const float* __restrict__ gamma,
                        const float* __restrict__ beta,
                        float* __restrict__ outp){
    __shared__ __align__(16) float sA[EMB], sC[EMB];
    int tid = threadIdx.x;
    const float* si = g_stats[layer][1];
    if (tid < EMB){
        float mean = si[tid] * (1.0f/NN);
        float var  = si[EMB + tid] * (1.0f/NN) - mean*mean;
        float a = gamma[tid] * rsqrtf(var + BN_EPS);
        sA[tid] = a;
        sC[tid] = beta[tid] - mean*a;
    }
    __syncthreads();
    int i = blockIdx.x*blockDim.x + tid;
    if (i < NN*16){
        int c4 = (i & 15) * 4;
        float4 a = *(const float4*)&sA[c4];
        float4 c = *(const float4*)&sC[c4];
        float4 t = ((const float4*)g_t2)[i];
        float4 h = ((const float4*)g_h)[i];
        float4 r;
        r.x = fmaxf(fmaf(t.x, a.x, c.x), 0.f) + h.x;
        r.y = fmaxf(fmaf(t.y, a.y, c.y), 0.f) + h.y;
        r.z = fmaxf(fmaf(t.z, a.z, c.z), 0.f) + h.z;
        r.w = fmaxf(fmaf(t.w, a.w, c.w), 0.f) + h.w;
        float4* dst = outp ? (float4*)outp : (float4*)g_h;
        dst[i] = r;
    }
}

extern "C" void kernel_launch(void* const* d_in, const int* in_sizes, int n_in,
                              void* d_out, int out_size){
    const float* x   = (const float*)d_in[0];
    const int*   ei  = (const int*)  d_in[1];
    const float* ew  = (const float*)d_in[3];
    const float* aew = (const float*)d_in[4];
    const float* aeb = (const float*)d_in[5];
    const float* W1  = (const float*)d_in[6];
    const float* b1  = (const float*)d_in[7];
    const float* g1  = (const float*)d_in[8];
    const float* be1 = (const float*)d_in[9];
    const float* W2  = (const float*)d_in[10];
    const float* b2  = (const float*)d_in[11];
    const float* go  = (const float*)d_in[12];
    const float* beo = (const float*)d_in[13];
    float* out = (float*)d_out;

    k_init   <<<(NN + 255)/256, 256>>>();
    k_hist   <<<(NE + 255)/256, 256>>>(ei);
    k_scan   <<<1, 1024>>>();
    k_scatter<<<(NE + 255)/256, 256>>>(ei, ew);

    int gb = (NN + 127)/128;
    k_gemm<0><<<gb, 128>>>(x, aew, aeb, 0, nullptr, nullptr);

    for (int l = 0; l < NL; l++){
        k_agg    <<<(NN + 7)/8, 256>>>();
        k_gemm<1><<<gb, 128>>>(nullptr, W1 + l*EMB*EMB, b1 + l*EMB, l, nullptr, nullptr);
        k_gemm<2><<<gb, 128>>>(nullptr, W2 + l*EMB*EMB, b2 + l*EMB, l, g1 + l*EMB, be1 + l*EMB);
        k_resid  <<<(NN*16 + 255)/256, 256>>>(l, go + l*EMB, beo + l*EMB,
                                              l == NL-1 ? out : nullptr);
    }
}